// round 16
// baseline (speedup 1.0000x reference)
#include <cuda_runtime.h>

// AtmLayer v9: v8 + select-free ext elu (log2-domain pre-scaled ext weights,
// -1 folded into output bias) + occupancy cap (10 blocks/SM).

#define TPB 128

typedef unsigned long long u64;
union F2U { u64 u; float2 f; };

__device__ __forceinline__ float2 fma2(float2 a, float2 b, float2 c) {
    F2U A, B, C, D; A.f = a; B.f = b; C.f = c;
    asm("fma.rn.f32x2 %0,%1,%2,%3;" : "=l"(D.u) : "l"(A.u), "l"(B.u), "l"(C.u));
    return D.f;
}
__device__ __forceinline__ float2 mul2(float2 a, float2 b) {
    F2U A, B, D; A.f = a; B.f = b;
    asm("mul.rn.f32x2 %0,%1,%2;" : "=l"(D.u) : "l"(A.u), "l"(B.u));
    return D.f;
}
__device__ __forceinline__ float2 add2(float2 a, float2 b) {
    F2U A, B, D; A.f = a; B.f = b;
    asm("add.rn.f32x2 %0,%1,%2;" : "=l"(D.u) : "l"(A.u), "l"(B.u));
    return D.f;
}
__device__ __forceinline__ float ex2_(float x) {
    float r; asm("ex2.approx.ftz.f32 %0,%1;" : "=f"(r) : "f"(x)); return r;
}

#define L2E 1.4426950408889634f
#define LN2 0.6931471805599453f

// comp idx: 0=h2o 1=h2o_sq 2=o3 3=co2 4=n2o 5=ch4 6=u
__constant__ int cNETS[29][7] = {
    {23, 0,52,65,74,77,86},
    {24, 1,53,66,75,78,87},
    {25, 2,54,67,76,79,88},
    {26, 3,80,-1,-1,-1,-1},
    {27, 4,81,-1,-1,-1,-1},
    {28, 5,68,-1,-1,-1,-1},
    {29, 6,69,-1,-1,-1,-1},
    {30, 3,82,-1,-1,-1,-1},
    {31, 4,83,-1,-1,-1,-1},
    {32, 9,70,-1,-1,-1,-1},
    {33,10,71,-1,-1,-1,-1},
    {34,11,84,-1,-1,-1,-1},
    {35,12,85,-1,-1,-1,-1},
    {36,13,72,-1,-1,-1,-1},
    {37,14,73,-1,-1,-1,-1},
    {38,15,89,-1,-1,-1,-1},
    {39,16,90,-1,-1,-1,-1},
    {40,17,55,91,-1,-1,-1},
    {41,18,56,92,-1,-1,-1},
    {42,19,57,93,-1,-1,-1},
    {43,20,58,94,-1,-1,-1},
    {44,21,59,95,-1,-1,-1},
    {45,22,60,96,-1,-1,-1},
    {46,-1,-1,-1,-1,-1,-1},
    {47,-1,-1,-1,-1,-1,-1},
    {48,61,-1,-1,-1,-1,-1},
    {49,62,-1,-1,-1,-1,-1},
    {50,63,97,-1,-1,-1,-1},
    {51,64,98,-1,-1,-1,-1},
};
__constant__ int cCIDX[29][7] = {
    {1,0,2,3,4,5,6},
    {1,0,2,3,4,5,6},
    {1,0,2,3,4,5,6},
    {1,0,5,0,0,0,0},
    {1,0,5,0,0,0,0},
    {1,0,3,0,0,0,0},
    {1,0,3,0,0,0,0},
    {1,0,5,0,0,0,0},
    {1,0,5,0,0,0,0},
    {1,0,3,0,0,0,0},
    {1,0,3,0,0,0,0},
    {1,0,5,0,0,0,0},
    {1,0,5,0,0,0,0},
    {1,0,3,0,0,0,0},
    {1,0,3,0,0,0,0},
    {1,0,6,0,0,0,0},
    {1,0,6,0,0,0,0},
    {1,0,2,6,0,0,0},
    {1,0,2,6,0,0,0},
    {1,0,2,6,0,0,0},
    {1,0,2,6,0,0,0},
    {1,0,2,6,0,0,0},
    {1,0,2,6,0,0,0},
    {1,0,0,0,0,0,0},
    {1,0,0,0,0,0,0},
    {1,2,0,0,0,0,0},
    {1,2,0,0,0,0,0},
    {1,2,6,0,0,0,0},
    {1,2,6,0,0,0,0},
};
__constant__ int cCNT[29] = {7,7,7,3,3,3,3,3,3,3,3,3,3,3,3,3,3,4,4,4,4,4,4,1,1,2,2,3,3};

struct __align__(16) GasNet {
    float2 gw[8][4];   // [u]: [0]=W1_row0*L2E dup, [1]=W1_row1*L2E dup,
                       //      [2]=W2*LN2 dup,       [3]=W2 dup
    float2 gb[8];      // b1 * L2E, dup
    float  bias;       // b2 - sum(W2)
    float  pad[3];
};
struct __align__(16) SmemT {
    GasNet g[7];
    float2 ew1[16][4];   // ext W1*L2E dup, [j][i]; read as 2x float4
    float2 evb[16][4];   // [j]: v0,v1,v2 dup, b1[j]*L2E dup; 2x float4
    float  misc[6];      // lw, iw, ebd0..2 (= eb_k - sum_j v_jk), pad
    const float* comp[7];
};

template<int CNT>
__device__ __forceinline__ void row_body(
    SmemT* sm, int r,
    const float* __restrict__ temp, const float* __restrict__ pressure,
    const float* __restrict__ comp_h2o, const float* __restrict__ comp_h2o_sq,
    const float* __restrict__ comp_o3, const float* __restrict__ comp_co2,
    const float* __restrict__ comp_n2o, const float* __restrict__ comp_ch4,
    const float* __restrict__ comp_u,
    const float* __restrict__ lwp, const float* __restrict__ iwp,
    const float* __restrict__ mu, const float* __restrict__ mu_bar,
    const float* __restrict__ gas_W1, const float* __restrict__ gas_b1,
    const float* __restrict__ gas_W2, const float* __restrict__ gas_b2,
    const float* __restrict__ lw_w, const float* __restrict__ iw_w,
    const float* __restrict__ ext_W1, const float* __restrict__ ext_b1,
    const float* __restrict__ ext_W2, const float* __restrict__ ext_b2,
    float* __restrict__ out, int B)
{
    const int tid = threadIdx.x;

    // ---- staging: transform + duplicate weights into packed layout ----
    #pragma unroll 2
    for (int i = tid; i < CNT * 33; i += TPB) {
        const int t = i / 33;
        const int k = i - t * 33;
        const int g = cNETS[r][t];
        GasNet& G = sm->g[t];
        if (k < 16) {
            const float w = gas_W1[g * 16 + k] * L2E;
            G.gw[k & 7][k >> 3] = make_float2(w, w);
        } else if (k < 24) {
            const float w = gas_b1[g * 8 + (k - 16)] * L2E;
            G.gb[k - 16] = make_float2(w, w);
        } else if (k < 32) {
            const float w = gas_W2[g * 8 + (k - 24)];
            G.gw[k - 24][2] = make_float2(w * LN2, w * LN2);
            G.gw[k - 24][3] = make_float2(w, w);
        } else {
            float s = 0.0f;
            #pragma unroll
            for (int u = 0; u < 8; ++u) s += gas_W2[g * 8 + u];
            G.bias = gas_b2[g] - s;
        }
    }
    for (int i = tid; i < 64; i += TPB) {
        const int ii = i >> 4, j = i & 15;
        const float w = ext_W1[r * 64 + i] * L2E;
        sm->ew1[j][ii] = make_float2(w, w);
    }
    for (int i = tid; i < 48; i += TPB) {
        const int j = i / 3, k = i - j * 3;
        const float w = ext_W2[r * 48 + i];
        sm->evb[j][k] = make_float2(w, w);
    }
    for (int i = tid; i < 16; i += TPB) {
        const float w = ext_b1[r * 16 + i] * L2E;
        sm->evb[i][3] = make_float2(w, w);
    }
    if (tid < 5) {
        float v;
        if      (tid == 0) v = lw_w[r];
        else if (tid == 1) v = iw_w[r];
        else {
            const int k = tid - 2;
            float s = 0.0f;
            #pragma unroll
            for (int j = 0; j < 16; ++j) s += ext_W2[r * 48 + j * 3 + k];
            v = ext_b2[r * 3 + k] - s;        // fold the elu "-1" into bias
        }
        sm->misc[tid] = v;
    }
    if (tid >= 8 && tid < 8 + CNT) {
        const int t = tid - 8;
        const float* ptrs[7] = {comp_h2o, comp_h2o_sq, comp_o3, comp_co2,
                                comp_n2o, comp_ch4, comp_u};
        sm->comp[t] = ptrs[cCIDX[r][t]];
    }
    __syncthreads();

    const int p = blockIdx.x * TPB + tid;      // pair index
    const int b0 = 2 * p;
    if (b0 + 1 >= B) return;

    const float2 X0 = reinterpret_cast<const float2*>(temp)[p];      // (A,B)
    const float2 X1 = reinterpret_cast<const float2*>(pressure)[p];

    // ---- gas nets: packed (A,B), split-accumulator elu ----
    float2 tau = make_float2(0.0f, 0.0f);
    #pragma unroll
    for (int t = 0; t < CNT; ++t) {
        const GasNet& G = sm->g[t];
        float2 acc1 = make_float2(0.0f, 0.0f);
        float2 acc2 = make_float2(0.0f, 0.0f);
        #pragma unroll
        for (int u = 0; u < 8; ++u) {
            const float4 q0 = *reinterpret_cast<const float4*>(&G.gw[u][0]);
            const float4 q1 = *reinterpret_cast<const float4*>(&G.gw[u][2]);
            const float2 wa = make_float2(q0.x, q0.y);
            const float2 wb = make_float2(q0.z, q0.w);
            const float2 vl = make_float2(q1.x, q1.y);
            const float2 vv = make_float2(q1.z, q1.w);
            const float2 bb = G.gb[u];
            const float2 zs = fma2(X1, wb, fma2(X0, wa, bb));
            const float2 mx = make_float2(fmaxf(zs.x, 0.0f), fmaxf(zs.y, 0.0f));
            const float2 ee = make_float2(ex2_(fminf(zs.x, 0.0f)),
                                          ex2_(fminf(zs.y, 0.0f)));
            acc1 = fma2(mx, vl, acc1);
            acc2 = fma2(ee, vv, acc2);
        }
        const float2 acc = add2(acc1, acc2);
        const float keA = fmaxf(acc.x + G.bias, 0.0f);
        const float keB = fmaxf(acc.y + G.bias, 0.0f);
        const float2 cc = reinterpret_cast<const float2*>(sm->comp[t])[p];
        tau = fma2(make_float2(keA, keB), cc, tau);
    }

    // ---- cloud terms + ext inputs ----
    const float2 LWP = reinterpret_cast<const float2*>(lwp)[p];
    const float2 IWP = reinterpret_cast<const float2*>(iwp)[p];
    const float2 MUv = reinterpret_cast<const float2*>(mu)[p];
    const float2 MUB = reinterpret_cast<const float2*>(mu_bar)[p];
    const float lwr = sm->misc[0], iwr = sm->misc[1];
    const float2 tlw = mul2(make_float2(lwr, lwr), LWP);
    const float2 tiw = mul2(make_float2(iwr, iwr), IWP);
    const float2 tt  = add2(tau, add2(tlw, tiw));
    const float2 rtt = make_float2(__fdividef(1.0f, tt.x), __fdividef(1.0f, tt.y));
    const float2 I1 = mul2(tlw, rtt);
    const float2 I2 = mul2(tiw, rtt);
    const float2 I3D = make_float2(tt.x * __fdividef(1.0f, MUv.x),
                                   tt.y * __fdividef(1.0f, MUv.y));
    const float2 I3F = make_float2(tt.x * __fdividef(1.0f, MUB.x),
                                   tt.y * __fdividef(1.0f, MUB.y));

    // ---- ext net: packed (A,B), log2-domain z, select-free elu ----
    const float eb0 = sm->misc[2], eb1v = sm->misc[3], eb2v = sm->misc[4];
    float2 ad0 = make_float2(eb0, eb0), ad1 = make_float2(eb1v, eb1v), ad2 = make_float2(eb2v, eb2v);
    float2 af0 = ad0, af1 = ad1, af2 = ad2;
    const float2 LN22 = make_float2(LN2, LN2);
    #pragma unroll
    for (int j = 0; j < 16; ++j) {
        const float4 e0 = *reinterpret_cast<const float4*>(&sm->ew1[j][0]);
        const float4 e1 = *reinterpret_cast<const float4*>(&sm->ew1[j][2]);
        const float4 e2 = *reinterpret_cast<const float4*>(&sm->evb[j][0]);
        const float4 e3 = *reinterpret_cast<const float4*>(&sm->evb[j][2]);
        const float2 w0  = make_float2(e0.x, e0.y);
        const float2 w1v = make_float2(e0.z, e0.w);
        const float2 w2v = make_float2(e1.x, e1.y);
        const float2 w3v = make_float2(e1.z, e1.w);
        const float2 v0  = make_float2(e2.x, e2.y);
        const float2 v1  = make_float2(e2.z, e2.w);
        const float2 v2  = make_float2(e3.x, e3.y);
        const float2 bj  = make_float2(e3.z, e3.w);
        const float2 base = fma2(I2, w1v, fma2(I1, w0, bj));
        const float2 zd = fma2(MUv, w3v, fma2(I3D, w2v, base));   // log2 domain
        const float2 zf = fma2(MUB, w3v, fma2(I3F, w2v, base));
        const float2 mxd = make_float2(fmaxf(zd.x, 0.0f), fmaxf(zd.y, 0.0f));
        const float2 eed = make_float2(ex2_(fminf(zd.x, 0.0f)),
                                       ex2_(fminf(zd.y, 0.0f)));
        const float2 mxf = make_float2(fmaxf(zf.x, 0.0f), fmaxf(zf.y, 0.0f));
        const float2 eef = make_float2(ex2_(fminf(zf.x, 0.0f)),
                                       ex2_(fminf(zf.y, 0.0f)));
        const float2 hd = fma2(mxd, LN22, eed);   // elu + 1 (the -1 is in bias)
        const float2 hf = fma2(mxf, LN22, eef);
        ad0 = fma2(hd, v0, ad0); ad1 = fma2(hd, v1, ad1); ad2 = fma2(hd, v2, ad2);
        af0 = fma2(hf, v0, af0); af1 = fma2(hf, v1, af1); af2 = fma2(hf, v2, af2);
    }

    const unsigned NB = (unsigned)B * 29u;
    const unsigned rb = (unsigned)r * (unsigned)B + (unsigned)b0;
    const unsigned ebase = rb * 3u;

    // softmax (direct, cols A+B) -> 3 float2 stores
    {
        const float a0 = fmaxf(ad0.x, 0.0f), a1 = fmaxf(ad1.x, 0.0f), a2 = fmaxf(ad2.x, 0.0f);
        const float m = fmaxf(a0, fmaxf(a1, a2));
        const float e0 = ex2_((a0 - m) * L2E), e1 = ex2_((a1 - m) * L2E), e2 = ex2_((a2 - m) * L2E);
        const float inv = __fdividef(1.0f, e0 + e1 + e2);
        const float b0v = fmaxf(ad0.y, 0.0f), b1v = fmaxf(ad1.y, 0.0f), b2v = fmaxf(ad2.y, 0.0f);
        const float mB = fmaxf(b0v, fmaxf(b1v, b2v));
        const float f0 = ex2_((b0v - mB) * L2E), f1 = ex2_((b1v - mB) * L2E), f2 = ex2_((b2v - mB) * L2E);
        const float invB = __fdividef(1.0f, f0 + f1 + f2);
        float2* o = reinterpret_cast<float2*>(out + 2u * NB + ebase);
        o[0] = make_float2(e0 * inv, e1 * inv);
        o[1] = make_float2(e2 * inv, f0 * invB);
        o[2] = make_float2(f1 * invB, f2 * invB);
    }
    // softmax (diffuse)
    {
        const float a0 = fmaxf(af0.x, 0.0f), a1 = fmaxf(af1.x, 0.0f), a2 = fmaxf(af2.x, 0.0f);
        const float m = fmaxf(a0, fmaxf(a1, a2));
        const float e0 = ex2_((a0 - m) * L2E), e1 = ex2_((a1 - m) * L2E), e2 = ex2_((a2 - m) * L2E);
        const float inv = __fdividef(1.0f, e0 + e1 + e2);
        const float b0v = fmaxf(af0.y, 0.0f), b1v = fmaxf(af1.y, 0.0f), b2v = fmaxf(af2.y, 0.0f);
        const float mB = fmaxf(b0v, fmaxf(b1v, b2v));
        const float f0 = ex2_((b0v - mB) * L2E), f1 = ex2_((b1v - mB) * L2E), f2 = ex2_((b2v - mB) * L2E);
        const float invB = __fdividef(1.0f, f0 + f1 + f2);
        float2* o = reinterpret_cast<float2*>(out + 5u * NB + ebase);
        o[0] = make_float2(e0 * inv, e1 * inv);
        o[1] = make_float2(e2 * inv, f0 * invB);
        o[2] = make_float2(f1 * invB, f2 * invB);
    }
    {
        const float2 nd = mul2(I3D, make_float2(-L2E, -L2E));
        const float2 nf = mul2(I3F, make_float2(-L2E, -L2E));
        reinterpret_cast<float2*>(out + rb)[0]      = make_float2(ex2_(nd.x), ex2_(nd.y));
        reinterpret_cast<float2*>(out + NB + rb)[0] = make_float2(ex2_(nf.x), ex2_(nf.y));
    }
}

__global__ void __launch_bounds__(TPB, 10)
atm_row_kernel(const float* __restrict__ temp,
               const float* __restrict__ pressure,
               const float* __restrict__ comp_h2o,
               const float* __restrict__ comp_h2o_sq,
               const float* __restrict__ comp_o3,
               const float* __restrict__ comp_co2,
               const float* __restrict__ comp_n2o,
               const float* __restrict__ comp_ch4,
               const float* __restrict__ comp_u,
               const float* __restrict__ lwp,
               const float* __restrict__ iwp,
               const float* __restrict__ mu,
               const float* __restrict__ mu_bar,
               const float* __restrict__ gas_W1,
               const float* __restrict__ gas_b1,
               const float* __restrict__ gas_W2,
               const float* __restrict__ gas_b2,
               const float* __restrict__ lw_w,
               const float* __restrict__ iw_w,
               const float* __restrict__ ext_W1,
               const float* __restrict__ ext_b1,
               const float* __restrict__ ext_W2,
               const float* __restrict__ ext_b2,
               float* __restrict__ out,
               int B)
{
    __shared__ SmemT sm;
    const int r = blockIdx.y;
    const int cnt = cCNT[r];
    #define ARGS &sm, r, temp, pressure, comp_h2o, comp_h2o_sq, comp_o3, comp_co2, \
                 comp_n2o, comp_ch4, comp_u, lwp, iwp, mu, mu_bar, gas_W1, gas_b1, \
                 gas_W2, gas_b2, lw_w, iw_w, ext_W1, ext_b1, ext_W2, ext_b2, out, B
    switch (cnt) {
        case 7: row_body<7>(ARGS); break;
        case 4: row_body<4>(ARGS); break;
        case 3: row_body<3>(ARGS); break;
        case 2: row_body<2>(ARGS); break;
        default: row_body<1>(ARGS); break;
    }
    #undef ARGS
}

extern "C" void kernel_launch(void* const* d_in, const int* in_sizes, int n_in,
                              void* d_out, int out_size)
{
    const int B = in_sizes[0];
    const int pairs = (B + 1) / 2;
    dim3 grid((pairs + TPB - 1) / TPB, 29);
    atm_row_kernel<<<grid, TPB>>>(
        (const float*)d_in[0],  (const float*)d_in[1],  (const float*)d_in[2],
        (const float*)d_in[3],  (const float*)d_in[4],  (const float*)d_in[5],
        (const float*)d_in[6],  (const float*)d_in[7],  (const float*)d_in[8],
        (const float*)d_in[9],  (const float*)d_in[10], (const float*)d_in[11],
        (const float*)d_in[12], (const float*)d_in[13], (const float*)d_in[14],
        (const float*)d_in[15], (const float*)d_in[16], (const float*)d_in[17],
        (const float*)d_in[18], (const float*)d_in[19], (const float*)d_in[20],
        (const float*)d_in[21], (const float*)d_in[22],
        (float*)d_out, B);
}

// round 17
// speedup vs baseline: 1.0258x; 1.0258x over previous
#include <cuda_runtime.h>

// AtmLayer v10: pack f32x2 over HIDDEN-UNIT pairs (gas u-pairs, ext j-pairs)
// instead of column pairs -> weights live un-duplicated in smem (half the LDS
// bytes/wavefronts). Both columns still computed per thread, sharing loads.
// Select-free elu everywhere; min via fma2(mx,-1,z).

#define TPB 128

typedef unsigned long long u64;
union F2U { u64 u; float2 f; };

__device__ __forceinline__ float2 fma2(float2 a, float2 b, float2 c) {
    F2U A, B, C, D; A.f = a; B.f = b; C.f = c;
    asm("fma.rn.f32x2 %0,%1,%2,%3;" : "=l"(D.u) : "l"(A.u), "l"(B.u), "l"(C.u));
    return D.f;
}
__device__ __forceinline__ float2 mul2(float2 a, float2 b) {
    F2U A, B, D; A.f = a; B.f = b;
    asm("mul.rn.f32x2 %0,%1,%2;" : "=l"(D.u) : "l"(A.u), "l"(B.u));
    return D.f;
}
__device__ __forceinline__ float2 add2(float2 a, float2 b) {
    F2U A, B, D; A.f = a; B.f = b;
    asm("add.rn.f32x2 %0,%1,%2;" : "=l"(D.u) : "l"(A.u), "l"(B.u));
    return D.f;
}
__device__ __forceinline__ float ex2_(float x) {
    float r; asm("ex2.approx.ftz.f32 %0,%1;" : "=f"(r) : "f"(x)); return r;
}

#define L2E 1.4426950408889634f
#define LN2 0.6931471805599453f

// comp idx: 0=h2o 1=h2o_sq 2=o3 3=co2 4=n2o 5=ch4 6=u
__constant__ int cNETS[29][7] = {
    {23, 0,52,65,74,77,86},
    {24, 1,53,66,75,78,87},
    {25, 2,54,67,76,79,88},
    {26, 3,80,-1,-1,-1,-1},
    {27, 4,81,-1,-1,-1,-1},
    {28, 5,68,-1,-1,-1,-1},
    {29, 6,69,-1,-1,-1,-1},
    {30, 3,82,-1,-1,-1,-1},
    {31, 4,83,-1,-1,-1,-1},
    {32, 9,70,-1,-1,-1,-1},
    {33,10,71,-1,-1,-1,-1},
    {34,11,84,-1,-1,-1,-1},
    {35,12,85,-1,-1,-1,-1},
    {36,13,72,-1,-1,-1,-1},
    {37,14,73,-1,-1,-1,-1},
    {38,15,89,-1,-1,-1,-1},
    {39,16,90,-1,-1,-1,-1},
    {40,17,55,91,-1,-1,-1},
    {41,18,56,92,-1,-1,-1},
    {42,19,57,93,-1,-1,-1},
    {43,20,58,94,-1,-1,-1},
    {44,21,59,95,-1,-1,-1},
    {45,22,60,96,-1,-1,-1},
    {46,-1,-1,-1,-1,-1,-1},
    {47,-1,-1,-1,-1,-1,-1},
    {48,61,-1,-1,-1,-1,-1},
    {49,62,-1,-1,-1,-1,-1},
    {50,63,97,-1,-1,-1,-1},
    {51,64,98,-1,-1,-1,-1},
};
__constant__ int cCIDX[29][7] = {
    {1,0,2,3,4,5,6},
    {1,0,2,3,4,5,6},
    {1,0,2,3,4,5,6},
    {1,0,5,0,0,0,0},
    {1,0,5,0,0,0,0},
    {1,0,3,0,0,0,0},
    {1,0,3,0,0,0,0},
    {1,0,5,0,0,0,0},
    {1,0,5,0,0,0,0},
    {1,0,3,0,0,0,0},
    {1,0,3,0,0,0,0},
    {1,0,5,0,0,0,0},
    {1,0,5,0,0,0,0},
    {1,0,3,0,0,0,0},
    {1,0,3,0,0,0,0},
    {1,0,6,0,0,0,0},
    {1,0,6,0,0,0,0},
    {1,0,2,6,0,0,0},
    {1,0,2,6,0,0,0},
    {1,0,2,6,0,0,0},
    {1,0,2,6,0,0,0},
    {1,0,2,6,0,0,0},
    {1,0,2,6,0,0,0},
    {1,0,0,0,0,0,0},
    {1,0,0,0,0,0,0},
    {1,2,0,0,0,0,0},
    {1,2,0,0,0,0,0},
    {1,2,6,0,0,0,0},
    {1,2,6,0,0,0,0},
};
__constant__ int cCNT[29] = {7,7,7,3,3,3,3,3,3,3,3,3,3,3,3,3,3,4,4,4,4,4,4,1,1,2,2,3,3};

// Per gas net, weights packed over u-pairs p=0..3 (NOT duplicated):
//   gw1[p] = (W1[0][2p], W1[0][2p+1], W1[1][2p], W1[1][2p+1]) * L2E
//   gv[p]  = (v[2p]*LN2, v[2p+1]*LN2, v[2p], v[2p+1])
//   gb[p]  = (b1[2p], b1[2p+1]) * L2E
//   bias   = b2 - sum(v)
struct __align__(16) GasNet {
    float4 gw1[4];
    float4 gv[4];
    float2 gb[4];
    float  bias;
    float  pad[3];
};
// Ext weights packed over j-pairs jp=0..7 (NOT duplicated):
//   ewA[jp]  = (w0[2j], w0[2j+1], w1[2j], w1[2j+1]) * L2E
//   ewB[jp]  = (w2[2j], w2[2j+1], w3[2j], w3[2j+1]) * L2E
//   evb0[jp] = (b1[2j]*L2E, b1[2j+1]*L2E, v0[2j], v0[2j+1])
//   evb1[jp] = (v1[2j], v1[2j+1], v2[2j], v2[2j+1])
struct __align__(16) SmemT {
    GasNet g[7];
    float4 ewA[8];
    float4 ewB[8];
    float4 evb0[8];
    float4 evb1[8];
    float  misc[6];      // lw, iw, ebd0..2 (= eb_k - sum_j v_jk)
    const float* comp[7];
};

__device__ __forceinline__ float2 lo2(float4 q) { return make_float2(q.x, q.y); }
__device__ __forceinline__ float2 hi2(float4 q) { return make_float2(q.z, q.w); }

template<int CNT>
__device__ __forceinline__ void row_body(
    SmemT* sm, int r,
    const float* __restrict__ temp, const float* __restrict__ pressure,
    const float* __restrict__ comp_h2o, const float* __restrict__ comp_h2o_sq,
    const float* __restrict__ comp_o3, const float* __restrict__ comp_co2,
    const float* __restrict__ comp_n2o, const float* __restrict__ comp_ch4,
    const float* __restrict__ comp_u,
    const float* __restrict__ lwp, const float* __restrict__ iwp,
    const float* __restrict__ mu, const float* __restrict__ mu_bar,
    const float* __restrict__ gas_W1, const float* __restrict__ gas_b1,
    const float* __restrict__ gas_W2, const float* __restrict__ gas_b2,
    const float* __restrict__ lw_w, const float* __restrict__ iw_w,
    const float* __restrict__ ext_W1, const float* __restrict__ ext_b1,
    const float* __restrict__ ext_W2, const float* __restrict__ ext_b2,
    float* __restrict__ out, int B)
{
    const int tid = threadIdx.x;

    // ---- staging (un-duplicated, pre-scaled) ----
    #pragma unroll 2
    for (int i = tid; i < CNT * 33; i += TPB) {
        const int t = i / 33;
        const int k = i - t * 33;
        const int g = cNETS[r][t];
        float* Gp = reinterpret_cast<float*>(&sm->g[t]);
        if (k < 16) {
            const int ii = k >> 3, u = k & 7;
            Gp[(u >> 1) * 4 + ii * 2 + (u & 1)] = gas_W1[g * 16 + k] * L2E;
        } else if (k < 24) {
            const int u = k - 16;
            Gp[32 + u] = gas_b1[g * 8 + u] * L2E;
        } else if (k < 32) {
            const int u = k - 24;
            const float v = gas_W2[g * 8 + u];
            Gp[16 + (u >> 1) * 4 + (u & 1)]     = v * LN2;
            Gp[16 + (u >> 1) * 4 + 2 + (u & 1)] = v;
        } else {
            float s = 0.0f;
            #pragma unroll
            for (int u = 0; u < 8; ++u) s += gas_W2[g * 8 + u];
            Gp[40] = gas_b2[g] - s;
        }
    }
    for (int i = tid; i < 64; i += TPB) {
        const int ii = i >> 4, j = i & 15;
        const int jp = j >> 1, l = j & 1;
        const float w = ext_W1[r * 64 + i] * L2E;
        if (ii < 2) reinterpret_cast<float*>(sm->ewA)[jp * 4 + ii * 2 + l] = w;
        else        reinterpret_cast<float*>(sm->ewB)[jp * 4 + (ii - 2) * 2 + l] = w;
    }
    for (int i = tid; i < 48; i += TPB) {
        const int j = i / 3, k = i - j * 3;
        const int jp = j >> 1, l = j & 1;
        const float w = ext_W2[r * 48 + i];
        if      (k == 0) reinterpret_cast<float*>(sm->evb0)[jp * 4 + 2 + l] = w;
        else if (k == 1) reinterpret_cast<float*>(sm->evb1)[jp * 4 + l]     = w;
        else             reinterpret_cast<float*>(sm->evb1)[jp * 4 + 2 + l] = w;
    }
    for (int i = tid; i < 16; i += TPB) {
        reinterpret_cast<float*>(sm->evb0)[(i >> 1) * 4 + (i & 1)] = ext_b1[r * 16 + i] * L2E;
    }
    if (tid < 5) {
        float v;
        if      (tid == 0) v = lw_w[r];
        else if (tid == 1) v = iw_w[r];
        else {
            const int k = tid - 2;
            float s = 0.0f;
            #pragma unroll
            for (int j = 0; j < 16; ++j) s += ext_W2[r * 48 + j * 3 + k];
            v = ext_b2[r * 3 + k] - s;        // fold the elu "-1" into bias
        }
        sm->misc[tid] = v;
    }
    if (tid >= 8 && tid < 8 + CNT) {
        const int t = tid - 8;
        const float* ptrs[7] = {comp_h2o, comp_h2o_sq, comp_o3, comp_co2,
                                comp_n2o, comp_ch4, comp_u};
        sm->comp[t] = ptrs[cCIDX[r][t]];
    }
    __syncthreads();

    const int p = blockIdx.x * TPB + tid;      // pair index
    const int b0 = 2 * p;
    if (b0 + 1 >= B) return;

    const float2 NEG1 = make_float2(-1.0f, -1.0f);
    const float2 LN22 = make_float2(LN2, LN2);

    const float2 X0 = reinterpret_cast<const float2*>(temp)[p];      // (A,B)
    const float2 X1 = reinterpret_cast<const float2*>(pressure)[p];
    const float2 X0A = make_float2(X0.x, X0.x), X0B = make_float2(X0.y, X0.y);
    const float2 X1A = make_float2(X1.x, X1.x), X1B = make_float2(X1.y, X1.y);

    // ---- gas nets: packed over u-pairs, both columns share weight loads ----
    float2 tau = make_float2(0.0f, 0.0f);
    #pragma unroll
    for (int t = 0; t < CNT; ++t) {
        const GasNet& G = sm->g[t];
        float2 a1A = make_float2(0.f, 0.f), a2A = make_float2(0.f, 0.f);
        float2 a1B = make_float2(0.f, 0.f), a2B = make_float2(0.f, 0.f);
        #pragma unroll
        for (int pp = 0; pp < 4; ++pp) {
            const float4 qw = G.gw1[pp];
            const float4 qv = G.gv[pp];
            const float2 bb = G.gb[pp];
            const float2 zA = fma2(X1A, hi2(qw), fma2(X0A, lo2(qw), bb));
            const float2 zB = fma2(X1B, hi2(qw), fma2(X0B, lo2(qw), bb));
            const float2 mxA = make_float2(fmaxf(zA.x, 0.f), fmaxf(zA.y, 0.f));
            const float2 mxB = make_float2(fmaxf(zB.x, 0.f), fmaxf(zB.y, 0.f));
            const float2 mnA = fma2(mxA, NEG1, zA);   // = min(z,0)
            const float2 mnB = fma2(mxB, NEG1, zB);
            const float2 eeA = make_float2(ex2_(mnA.x), ex2_(mnA.y));
            const float2 eeB = make_float2(ex2_(mnB.x), ex2_(mnB.y));
            a1A = fma2(mxA, lo2(qv), a1A);
            a2A = fma2(eeA, hi2(qv), a2A);
            a1B = fma2(mxB, lo2(qv), a1B);
            a2B = fma2(eeB, hi2(qv), a2B);
        }
        const float2 sA = add2(a1A, a2A);
        const float2 sB = add2(a1B, a2B);
        const float keA = fmaxf(sA.x + sA.y + G.bias, 0.0f);
        const float keB = fmaxf(sB.x + sB.y + G.bias, 0.0f);
        const float2 cc = reinterpret_cast<const float2*>(sm->comp[t])[p];
        tau = fma2(make_float2(keA, keB), cc, tau);
    }

    // ---- cloud terms + ext inputs ----
    const float2 LWP = reinterpret_cast<const float2*>(lwp)[p];
    const float2 IWP = reinterpret_cast<const float2*>(iwp)[p];
    const float2 MUp = reinterpret_cast<const float2*>(mu)[p];
    const float2 MBp = reinterpret_cast<const float2*>(mu_bar)[p];
    const float lwr = sm->misc[0], iwr = sm->misc[1];
    const float2 tlw = mul2(make_float2(lwr, lwr), LWP);
    const float2 tiw = mul2(make_float2(iwr, iwr), IWP);
    const float2 tt  = add2(tau, add2(tlw, tiw));
    const float2 rtt = make_float2(__fdividef(1.0f, tt.x), __fdividef(1.0f, tt.y));
    const float2 i1  = mul2(tlw, rtt);
    const float2 i2  = mul2(tiw, rtt);
    const float i3dA = tt.x * __fdividef(1.0f, MUp.x);
    const float i3dB = tt.y * __fdividef(1.0f, MUp.y);
    const float i3fA = tt.x * __fdividef(1.0f, MBp.x);
    const float i3fB = tt.y * __fdividef(1.0f, MBp.y);

    // duplicated packed inputs (per column)
    const float2 I1A = make_float2(i1.x, i1.x),  I1B = make_float2(i1.y, i1.y);
    const float2 I2A = make_float2(i2.x, i2.x),  I2B = make_float2(i2.y, i2.y);
    const float2 I3DA = make_float2(i3dA, i3dA), I3DB = make_float2(i3dB, i3dB);
    const float2 I3FA = make_float2(i3fA, i3fA), I3FB = make_float2(i3fB, i3fB);
    const float2 MUA = make_float2(MUp.x, MUp.x), MUB2 = make_float2(MUp.y, MUp.y);
    const float2 MBA = make_float2(MBp.x, MBp.x), MBB = make_float2(MBp.y, MBp.y);

    // ---- ext net: packed over j-pairs; 4 streams (A/B x dir/dif) ----
    const float eb0 = sm->misc[2], eb1v = sm->misc[3], eb2v = sm->misc[4];
    float2 aAd0 = make_float2(eb0, 0.f), aAd1 = make_float2(eb1v, 0.f), aAd2 = make_float2(eb2v, 0.f);
    float2 aAf0 = aAd0, aAf1 = aAd1, aAf2 = aAd2;
    float2 aBd0 = aAd0, aBd1 = aAd1, aBd2 = aAd2;
    float2 aBf0 = aAd0, aBf1 = aAd1, aBf2 = aAd2;
    #pragma unroll
    for (int jp = 0; jp < 8; ++jp) {
        const float4 eA  = sm->ewA[jp];
        const float4 eB  = sm->ewB[jp];
        const float4 q0  = sm->evb0[jp];
        const float4 q1  = sm->evb1[jp];
        const float2 w0p = lo2(eA), w1p = hi2(eA);
        const float2 w2p = lo2(eB), w3p = hi2(eB);
        const float2 bp  = lo2(q0), v0p = hi2(q0);
        const float2 v1p = lo2(q1), v2p = hi2(q1);

        const float2 baseA = fma2(I2A, w1p, fma2(I1A, w0p, bp));
        const float2 baseB = fma2(I2B, w1p, fma2(I1B, w0p, bp));
        const float2 zAd = fma2(MUA,  w3p, fma2(I3DA, w2p, baseA));
        const float2 zAf = fma2(MBA,  w3p, fma2(I3FA, w2p, baseA));
        const float2 zBd = fma2(MUB2, w3p, fma2(I3DB, w2p, baseB));
        const float2 zBf = fma2(MBB,  w3p, fma2(I3FB, w2p, baseB));

        const float2 mAd = make_float2(fmaxf(zAd.x, 0.f), fmaxf(zAd.y, 0.f));
        const float2 mAf = make_float2(fmaxf(zAf.x, 0.f), fmaxf(zAf.y, 0.f));
        const float2 mBd = make_float2(fmaxf(zBd.x, 0.f), fmaxf(zBd.y, 0.f));
        const float2 mBf = make_float2(fmaxf(zBf.x, 0.f), fmaxf(zBf.y, 0.f));
        const float2 nAd = fma2(mAd, NEG1, zAd);
        const float2 nAf = fma2(mAf, NEG1, zAf);
        const float2 nBd = fma2(mBd, NEG1, zBd);
        const float2 nBf = fma2(mBf, NEG1, zBf);
        const float2 eAd = make_float2(ex2_(nAd.x), ex2_(nAd.y));
        const float2 eAf = make_float2(ex2_(nAf.x), ex2_(nAf.y));
        const float2 eBd = make_float2(ex2_(nBd.x), ex2_(nBd.y));
        const float2 eBf = make_float2(ex2_(nBf.x), ex2_(nBf.y));
        const float2 hAd = fma2(mAd, LN22, eAd);   // elu+1 (the -1 is in bias)
        const float2 hAf = fma2(mAf, LN22, eAf);
        const float2 hBd = fma2(mBd, LN22, eBd);
        const float2 hBf = fma2(mBf, LN22, eBf);

        aAd0 = fma2(hAd, v0p, aAd0); aAd1 = fma2(hAd, v1p, aAd1); aAd2 = fma2(hAd, v2p, aAd2);
        aAf0 = fma2(hAf, v0p, aAf0); aAf1 = fma2(hAf, v1p, aAf1); aAf2 = fma2(hAf, v2p, aAf2);
        aBd0 = fma2(hBd, v0p, aBd0); aBd1 = fma2(hBd, v1p, aBd1); aBd2 = fma2(hBd, v2p, aBd2);
        aBf0 = fma2(hBf, v0p, aBf0); aBf1 = fma2(hBf, v1p, aBf1); aBf2 = fma2(hBf, v2p, aBf2);
    }

    const unsigned NB = (unsigned)B * 29u;
    const unsigned rb = (unsigned)r * (unsigned)B + (unsigned)b0;
    const unsigned ebase = rb * 3u;

    // softmax (direct, cols A+B) -> 3 float2 stores
    {
        const float a0 = fmaxf(aAd0.x + aAd0.y, 0.0f);
        const float a1 = fmaxf(aAd1.x + aAd1.y, 0.0f);
        const float a2 = fmaxf(aAd2.x + aAd2.y, 0.0f);
        const float m = fmaxf(a0, fmaxf(a1, a2));
        const float e0 = ex2_((a0 - m) * L2E), e1 = ex2_((a1 - m) * L2E), e2 = ex2_((a2 - m) * L2E);
        const float inv = __fdividef(1.0f, e0 + e1 + e2);
        const float b0v = fmaxf(aBd0.x + aBd0.y, 0.0f);
        const float b1v = fmaxf(aBd1.x + aBd1.y, 0.0f);
        const float b2v = fmaxf(aBd2.x + aBd2.y, 0.0f);
        const float mB = fmaxf(b0v, fmaxf(b1v, b2v));
        const float f0 = ex2_((b0v - mB) * L2E), f1 = ex2_((b1v - mB) * L2E), f2 = ex2_((b2v - mB) * L2E);
        const float invB = __fdividef(1.0f, f0 + f1 + f2);
        float2* o = reinterpret_cast<float2*>(out + 2u * NB + ebase);
        o[0] = make_float2(e0 * inv, e1 * inv);
        o[1] = make_float2(e2 * inv, f0 * invB);
        o[2] = make_float2(f1 * invB, f2 * invB);
    }
    // softmax (diffuse)
    {
        const float a0 = fmaxf(aAf0.x + aAf0.y, 0.0f);
        const float a1 = fmaxf(aAf1.x + aAf1.y, 0.0f);
        const float a2 = fmaxf(aAf2.x + aAf2.y, 0.0f);
        const float m = fmaxf(a0, fmaxf(a1, a2));
        const float e0 = ex2_((a0 - m) * L2E), e1 = ex2_((a1 - m) * L2E), e2 = ex2_((a2 - m) * L2E);
        const float inv = __fdividef(1.0f, e0 + e1 + e2);
        const float b0v = fmaxf(aBf0.x + aBf0.y, 0.0f);
        const float b1v = fmaxf(aBf1.x + aBf1.y, 0.0f);
        const float b2v = fmaxf(aBf2.x + aBf2.y, 0.0f);
        const float mB = fmaxf(b0v, fmaxf(b1v, b2v));
        const float f0 = ex2_((b0v - mB) * L2E), f1 = ex2_((b1v - mB) * L2E), f2 = ex2_((b2v - mB) * L2E);
        const float invB = __fdividef(1.0f, f0 + f1 + f2);
        float2* o = reinterpret_cast<float2*>(out + 5u * NB + ebase);
        o[0] = make_float2(e0 * inv, e1 * inv);
        o[1] = make_float2(e2 * inv, f0 * invB);
        o[2] = make_float2(f1 * invB, f2 * invB);
    }
    reinterpret_cast<float2*>(out + rb)[0] =
        make_float2(ex2_(-i3dA * L2E), ex2_(-i3dB * L2E));
    reinterpret_cast<float2*>(out + NB + rb)[0] =
        make_float2(ex2_(-i3fA * L2E), ex2_(-i3fB * L2E));
}

__global__ void __launch_bounds__(TPB, 7)
atm_row_kernel(const float* __restrict__ temp,
               const float* __restrict__ pressure,
               const float* __restrict__ comp_h2o,
               const float* __restrict__ comp_h2o_sq,
               const float* __restrict__ comp_o3,
               const float* __restrict__ comp_co2,
               const float* __restrict__ comp_n2o,
               const float* __restrict__ comp_ch4,
               const float* __restrict__ comp_u,
               const float* __restrict__ lwp,
               const float* __restrict__ iwp,
               const float* __restrict__ mu,
               const float* __restrict__ mu_bar,
               const float* __restrict__ gas_W1,
               const float* __restrict__ gas_b1,
               const float* __restrict__ gas_W2,
               const float* __restrict__ gas_b2,
               const float* __restrict__ lw_w,
               const float* __restrict__ iw_w,
               const float* __restrict__ ext_W1,
               const float* __restrict__ ext_b1,
               const float* __restrict__ ext_W2,
               const float* __restrict__ ext_b2,
               float* __restrict__ out,
               int B)
{
    __shared__ SmemT sm;
    const int r = blockIdx.y;
    const int cnt = cCNT[r];
    #define ARGS &sm, r, temp, pressure, comp_h2o, comp_h2o_sq, comp_o3, comp_co2, \
                 comp_n2o, comp_ch4, comp_u, lwp, iwp, mu, mu_bar, gas_W1, gas_b1, \
                 gas_W2, gas_b2, lw_w, iw_w, ext_W1, ext_b1, ext_W2, ext_b2, out, B
    switch (cnt) {
        case 7: row_body<7>(ARGS); break;
        case 4: row_body<4>(ARGS); break;
        case 3: row_body<3>(ARGS); break;
        case 2: row_body<2>(ARGS); break;
        default: row_body<1>(ARGS); break;
    }
    #undef ARGS
}

extern "C" void kernel_launch(void* const* d_in, const int* in_sizes, int n_in,
                              void* d_out, int out_size)
{
    const int B = in_sizes[0];
    const int pairs = (B + 1) / 2;
    dim3 grid((pairs + TPB - 1) / TPB, 29);
    atm_row_kernel<<<grid, TPB>>>(
        (const float*)d_in[0],  (const float*)d_in[1],  (const float*)d_in[2],
        (const float*)d_in[3],  (const float*)d_in[4],  (const float*)d_in[5],
        (const float*)d_in[6],  (const float*)d_in[7],  (const float*)d_in[8],
        (const float*)d_in[9],  (const float*)d_in[10], (const float*)d_in[11],
        (const float*)d_in[12], (const float*)d_in[13], (const float*)d_in[14],
        (const float*)d_in[15], (const float*)d_in[16], (const float*)d_in[17],
        (const float*)d_in[18], (const float*)d_in[19], (const float*)d_in[20],
        (const float*)d_in[21], (const float*)d_in[22],
        (float*)d_out, B);
}